// round 12
// baseline (speedup 1.0000x reference)
#include <cuda_runtime.h>
#include <cuda_bf16.h>
#include <math.h>

// ---------------- problem constants ----------------
constexpr int kN  = 2048;
constexpr int kC  = 256;
constexpr int kCO = 128;
constexpr int kM  = 8 * kN;      // 16384
constexpr int kG  = 66;
constexpr int kG3 = kG * kG * kG;

// ---------------- scratch globals (NEVER passed as kernel args from host) ----
__device__ __nv_bfloat16 g_hhi [(kN + 1) * kC];
__device__ __nv_bfloat16 g_hlo [(kN + 1) * kC];
__device__ __nv_bfloat16 g_h1hi[(kM + 1) * kCO];
__device__ __nv_bfloat16 g_h1lo[(kM + 1) * kCO];
__device__ float g_h1acc[kM * kCO];
__device__ float g_skip [kN * kCO];
__device__ int   g_grid[kG3];
__device__ int   g_nidx [kM * 27];
__device__ int   g_nidx1[kM * 27];
__device__ int   g_mask[kM];
__device__ int   g_cnt;
__device__ int   g_list[kM];
__device__ int   g_in1 [kM * 27 + 27 * 128], g_out1[kM * 27 + 27 * 128];
__device__ int   g_in2 [kM * 27 + 27 * 128], g_out2[kM * 27 + 27 * 128];
__device__ int   g_cnt1[27], g_cnt2[27];
// transposed bf16 weights: [27][128(n)][CIN(c)]
__device__ __nv_bfloat16 g_w1hi[27 * 128 * kC],  g_w1lo[27 * 128 * kC];
__device__ __nv_bfloat16 g_w2hi[27 * 128 * kCO], g_w2lo[27 * 128 * kCO];

// ---------------- ptx helpers ----------------
__device__ __forceinline__ unsigned smem_u32(const void* p) {
    unsigned a;
    asm("{ .reg .u64 t; cvta.to.shared.u64 t, %1; cvt.u32.u64 %0, t; }"
        : "=r"(a) : "l"(p));
    return a;
}
__device__ __forceinline__ void ldsm4(unsigned* r, unsigned addr) {
    asm volatile("ldmatrix.sync.aligned.m8n8.x4.shared.b16 {%0,%1,%2,%3}, [%4];"
                 : "=r"(r[0]), "=r"(r[1]), "=r"(r[2]), "=r"(r[3]) : "r"(addr));
}
__device__ __forceinline__ void mma16816(float* d, const unsigned* a,
                                         const unsigned* b) {
    asm volatile(
        "mma.sync.aligned.m16n8k16.row.col.f32.bf16.bf16.f32 "
        "{%0,%1,%2,%3}, {%4,%5,%6,%7}, {%8,%9}, {%0,%1,%2,%3};"
        : "+f"(d[0]), "+f"(d[1]), "+f"(d[2]), "+f"(d[3])
        : "r"(a[0]), "r"(a[1]), "r"(a[2]), "r"(a[3]), "r"(b[0]), "r"(b[1]));
}
__device__ __forceinline__ void red_v4(float* p, float4 v) {
    asm volatile("red.global.add.v4.f32 [%0], {%1, %2, %3, %4};"
                 :: "l"(p), "f"(v.x), "f"(v.y), "f"(v.z), "f"(v.w) : "memory");
}
// segment start/length from per-tap counts (padded to 128)
__device__ __forceinline__ int seg_start(const int* __restrict__ cnt,
                                         int k, int& plen) {
    int s = 0;
    for (int i = 0; i < k; ++i) s += (cnt[i] + 127) & ~127;
    plen = (cnt[k] + 127) & ~127;
    return s;
}

// ---------------- fused prep: zero + coalesced weight transpose + grid -------
// NOTE: the child->grid scatter is a SEPARATE subsequent launch; a sentinel
// write racing a scatter write within one launch silently drops voxels.
constexpr int PB0 = (kM * kCO) / 256;          // 8192  zero h1acc/out
constexpr int PBS = (kN * kCO) / 256;          // 1024  zero g_skip
constexpr int PT1 = 27 * 8 * 4;                // 864   w1 32x32 transpose tiles
constexpr int PT2 = 27 * 4 * 4;                // 432   w2 tiles
constexpr int PB3 = (kG3 + 255) / 256;         // 1124  grid sentinel
constexpr int PREP_BLOCKS = PB0 + PBS + PT1 + PT2 + PB3 + 1;

__global__ void prep_kernel(float* __restrict__ out,
                            const float* __restrict__ c1w,
                            const float* __restrict__ c2w) {
    __shared__ float sT[32][33];
    const int b = blockIdx.x, t = threadIdx.x;
    if (b < PB0) {
        int i = b * 256 + t;
        g_h1acc[i] = 0.f;
        out[i] = 0.f;
    } else if (b < PB0 + PBS) {
        g_skip[(b - PB0) * 256 + t] = 0.f;
    } else if (b < PB0 + PBS + PT1) {
        // w1: [27][256(c)][128(n)] -> [27][128(n)][256(c)], 32x32 tiles
        int b1 = b - PB0 - PBS;
        int k = b1 >> 5, r = b1 & 31;
        int c0 = (r >> 2) * 32, n0 = (r & 3) * 32;
        const float* wk = c1w + (size_t)k * kC * 128;
        int nx = t & 31, cy = t >> 5;
        #pragma unroll
        for (int i = 0; i < 4; ++i)
            sT[cy + 8 * i][nx] = wk[(size_t)(c0 + cy + 8 * i) * 128 + n0 + nx];
        __syncthreads();
        int cx = t & 31, ny = t >> 5;
        #pragma unroll
        for (int i = 0; i < 4; ++i) {
            float v = sT[cx][ny + 8 * i];
            __nv_bfloat16 h = __float2bfloat16(v);
            size_t o = (size_t)k * 128 * kC + (size_t)(n0 + ny + 8 * i) * kC + c0 + cx;
            g_w1hi[o] = h;
            g_w1lo[o] = __float2bfloat16(v - __bfloat162float(h));
        }
    } else if (b < PB0 + PBS + PT1 + PT2) {
        // w2: [27][128(c)][128(n)] -> [27][128(n)][128(c)]
        int b2 = b - PB0 - PBS - PT1;
        int k = b2 >> 4, r = b2 & 15;
        int c0 = (r >> 2) * 32, n0 = (r & 3) * 32;
        const float* wk = c2w + (size_t)k * kCO * 128;
        int nx = t & 31, cy = t >> 5;
        #pragma unroll
        for (int i = 0; i < 4; ++i)
            sT[cy + 8 * i][nx] = wk[(size_t)(c0 + cy + 8 * i) * 128 + n0 + nx];
        __syncthreads();
        int cx = t & 31, ny = t >> 5;
        #pragma unroll
        for (int i = 0; i < 4; ++i) {
            float v = sT[cx][ny + 8 * i];
            __nv_bfloat16 h = __float2bfloat16(v);
            size_t o = (size_t)k * 128 * kCO + (size_t)(n0 + ny + 8 * i) * kCO + c0 + cx;
            g_w2hi[o] = h;
            g_w2lo[o] = __float2bfloat16(v - __bfloat162float(h));
        }
    } else if (b < PB0 + PBS + PT1 + PT2 + PB3) {
        int i = (b - PB0 - PBS - PT1 - PT2) * 256 + t;
        if (i < kG3) g_grid[i] = kM;
    } else {
        if (t < kC)  { g_hhi[kN * kC + t] = __float2bfloat16(0.f);
                       g_hlo[kN * kC + t] = __float2bfloat16(0.f); }
        if (t < kCO) { g_h1hi[kM * kCO + t] = __float2bfloat16(0.f);
                       g_h1lo[kM * kCO + t] = __float2bfloat16(0.f); }
        if (t == 0)  g_cnt = 0;
        if (t < 27)  { g_cnt1[t] = 0; g_cnt2[t] = 0; }
    }
}

// ---------------- child scatter (separate launch: ordered AFTER sentinel) ----
__global__ void scatter_kernel(const int* __restrict__ coords) {
    int m = blockIdx.x * 256 + threadIdx.x;
    int n = m >> 3, j = m & 7;
    int cx = coords[n * 3 + 0] * 2 + ((j >> 2) & 1);
    int cy = coords[n * 3 + 1] * 2 + ((j >> 1) & 1);
    int cz = coords[n * 3 + 2] * 2 + (j & 1);
    g_grid[((cx + 1) * kG + (cy + 1)) * kG + (cz + 1)] = m;
}

// ---------------- per-parent: subdiv + mask + compact + LN + SiLU ------------
__global__ void row_kernel(const float* __restrict__ feats,
                           const float* __restrict__ n1w,
                           const float* __restrict__ n1b,
                           const float* __restrict__ sdw,
                           const float* __restrict__ sdb,
                           float* __restrict__ subdiv_out) {
    const int n = blockIdx.x;
    const int t = threadIdx.x;           // 256
    const int wid = t >> 5, lane = t & 31;
    __shared__ float sf[kC];
    __shared__ float red[8];
    __shared__ int   s_act[8];

    float x = feats[n * kC + t];
    sf[t] = x;
    __syncthreads();

    {
        float p = 0.f;
        #pragma unroll
        for (int i = 0; i < 8; ++i) {
            int c = lane + i * 32;
            p += sf[c] * sdw[c * 8 + wid];
        }
        #pragma unroll
        for (int o = 16; o; o >>= 1) p += __shfl_xor_sync(0xffffffffu, p, o);
        if (lane == 0) {
            p += sdb[wid];
            subdiv_out[n * 8 + wid] = p;
            int act = (p > 0.f) ? 1 : 0;
            g_mask[n * 8 + wid] = act;
            s_act[wid] = act;
        }
    }

    float s = x;
    #pragma unroll
    for (int o = 16; o; o >>= 1) s += __shfl_xor_sync(0xffffffffu, s, o);
    if (lane == 0) red[wid] = s;
    __syncthreads();

    if (wid == 0) {
        bool act = (lane < 8) && (s_act[lane] != 0);
        unsigned ball = __ballot_sync(0xffffffffu, act);
        int c = __popc(ball);
        int base = 0;
        if (lane == 0 && c) base = atomicAdd(&g_cnt, c);
        base = __shfl_sync(0xffffffffu, base, 0);
        if (act) g_list[base + __popc(ball & ((1u << lane) - 1u))] = n * 8 + lane;
    }

    float tot = 0.f;
    #pragma unroll
    for (int i = 0; i < 8; ++i) tot += red[i];
    const float mean = tot * (1.f / kC);
    const float d = x - mean;
    float s2 = d * d;
    #pragma unroll
    for (int o = 16; o; o >>= 1) s2 += __shfl_xor_sync(0xffffffffu, s2, o);
    __syncthreads();
    if (lane == 0) red[wid] = s2;
    __syncthreads();
    float vtot = 0.f;
    #pragma unroll
    for (int i = 0; i < 8; ++i) vtot += red[i];
    const float var = vtot * (1.f / kC);
    const float y = d * rsqrtf(var + 1e-6f) * n1w[t] + n1b[t];
    const float h = y / (1.f + expf(-y));
    __nv_bfloat16 hh = __float2bfloat16(h);
    g_hhi[n * kC + t] = hh;
    g_hlo[n * kC + t] = __float2bfloat16(h - __bfloat162float(hh));
}

// ---------------- neighbor table + fused tap counting (64 x 9 blocks) --------
__global__ void nidx_kernel(const int* __restrict__ coords) {
    __shared__ int c1[3], c2[3];
    const int t = threadIdx.x;
    const int lane = t & 31;
    const int k0 = blockIdx.y * 3;
    if (t < 3) { c1[t] = 0; c2[t] = 0; }
    __syncthreads();

    int m = blockIdx.x * 256 + t;
    int n = m >> 3, j = m & 7;
    int gx = coords[n * 3 + 0] * 2 + ((j >> 2) & 1) + 1;
    int gy = coords[n * 3 + 1] * 2 + ((j >> 1) & 1) + 1;
    int gz = coords[n * 3 + 2] * 2 + (j & 1) + 1;
    const int msk = g_mask[m];
    #pragma unroll
    for (int kk = 0; kk < 3; ++kk) {
        int k = k0 + kk;
        int dx = k / 9 - 1, dy = (k / 3) % 3 - 1, dz = k % 3 - 1;
        int nb = g_grid[((gx + dx) * kG + (gy + dy)) * kG + (gz + dz)];
        g_nidx[m * 27 + k] = nb;
        int in1 = (nb == kM) ? kN : (g_mask[nb] ? (nb >> 3) : kN);
        g_nidx1[m * 27 + k] = in1;
        unsigned b1 = __ballot_sync(0xffffffffu, in1 != kN);
        unsigned b2 = __ballot_sync(0xffffffffu, msk && (nb != kM));
        if (lane == 0) {
            if (b1) atomicAdd(&c1[kk], __popc(b1));
            if (b2) atomicAdd(&c2[kk], __popc(b2));
        }
    }
    __syncthreads();
    if (t < 3) {
        if (c1[t]) atomicAdd(&g_cnt1[k0 + t], c1[t]);
        if (c2[t]) atomicAdd(&g_cnt2[k0 + t], c2[t]);
    }
}

// ---------------- fill both pair lists in one launch (54 blocks) -------------
__device__ __forceinline__ bool tap_flag_rt(int mode, int m, int k, int& in_id) {
    if (mode == 1) {
        in_id = g_nidx1[m * 27 + k];
        return in_id != kN;
    } else {
        in_id = g_nidx[m * 27 + k];
        return g_mask[m] && (in_id != kM);
    }
}

__global__ void tap_fill_kernel() {
    const int mode = (blockIdx.x < 27) ? 1 : 2;
    const int k = blockIdx.x % 27;
    const int t = threadIdx.x;
    int* __restrict__ pin  = (mode == 1) ? g_in1  : g_in2;
    int* __restrict__ pout = (mode == 1) ? g_out1 : g_out2;
    int plen;
    const int start = seg_start((mode == 1) ? g_cnt1 : g_cnt2, k, plen);

    int cnt = 0;
    #pragma unroll 4
    for (int r = 0; r < 64; ++r) {
        int in_id;
        if (tap_flag_rt(mode, t * 64 + r, k, in_id)) ++cnt;
    }
    // Hillis-Steele inclusive scan over 256 counts
    __shared__ int sh[256];
    sh[t] = cnt;
    __syncthreads();
    #pragma unroll
    for (int off = 1; off < 256; off <<= 1) {
        int u = (t >= off) ? sh[t - off] : 0;
        __syncthreads();
        sh[t] += u;
        __syncthreads();
    }
    int w = start + sh[t] - cnt;      // exclusive prefix
    const int tot = sh[255];
    for (int r = 0; r < 64; ++r) {
        int m = t * 64 + r, in_id;
        if (tap_flag_rt(mode, m, k, in_id)) {
            pin[w] = in_id;
            pout[w] = m;
            ++w;
        }
    }
    for (int i = tot + t; i < plen; i += 256) {
        pin[start + i] = (mode == 1) ? kN : kM;   // zero bf16 rows
        pout[start + i] = -1;
    }
}

// ---------------- tensor-core tap GEMM via mma.sync + ldmatrix ---------------
// Block tile M=128 x N=128, BK=32, 256 threads (8 warps as 4x2, warp 32x64).
// Depth-2 register prefetch, ldmatrix.x4 fragments, smem-transposed red.v4
// scatter. Globals selected via MODE template.
template <int MODE>
__global__ void __launch_bounds__(256)
tapgemm_mma(float* __restrict__ ext_out)
{
    constexpr int CIN = (MODE == 1) ? kC : kCO;
    constexpr int BK  = 32;
    constexpr int NCH = CIN / BK;
    constexpr int LDB = 80;                 // tile row stride in bytes (40 bf16)

    // 4 bf16 tiles (40960B) aliased with the fp32 transpose buffer (33792B)
    __shared__ __align__(16) char smem_raw[40960];
    __shared__ int sIdx[128], sOut[128];
    __nv_bfloat16* Ahi = (__nv_bfloat16*)(smem_raw);
    __nv_bfloat16* Alo = (__nv_bfloat16*)(smem_raw + 10240);
    __nv_bfloat16* Bhi = (__nv_bfloat16*)(smem_raw + 20480);
    __nv_bfloat16* Blo = (__nv_bfloat16*)(smem_raw + 30720);
    float* T = (float*)smem_raw;            // 64 x 132 floats

    const int k = blockIdx.x >> 7;
    const int s = blockIdx.x & 127;
    int plen;
    const int segs = seg_start((MODE == 1) ? g_cnt1 : g_cnt2, k, plen);
    if (s * 128 >= plen) return;
    const int base = segs + s * 128;

    const __nv_bfloat16* __restrict__ shi = (MODE == 1) ? g_hhi : g_h1hi;
    const __nv_bfloat16* __restrict__ slo = (MODE == 1) ? g_hlo : g_h1lo;
    const __nv_bfloat16* __restrict__ whi = (MODE == 1) ? g_w1hi : g_w2hi;
    const __nv_bfloat16* __restrict__ wlo = (MODE == 1) ? g_w1lo : g_w2lo;
    const int* __restrict__ pin  = (MODE == 1) ? g_in1  : g_in2;
    const int* __restrict__ pout = (MODE == 1) ? g_out1 : g_out2;
    float* __restrict__ dstbase  = (MODE == 1) ? g_h1acc : ext_out;

    const int t = threadIdx.x;
    if (t < 128) {
        sIdx[t] = pin[base + t];
        sOut[t] = pout[base + t];
    }
    __syncthreads();

    const unsigned uAhi = smem_u32(Ahi), uAlo = smem_u32(Alo);
    const unsigned uBhi = smem_u32(Bhi), uBlo = smem_u32(Blo);

    const int warp = t >> 5, lane = t & 31;
    const int g = lane >> 2, tid = lane & 3;
    const int wm = (warp & 3) * 32;    // m offset
    const int wn = (warp >> 2) * 64;   // n offset

    // ldmatrix lane addressing (PTX x4 spec)
    const int a_row  = lane & 15;
    const int a_koff = (lane >> 4) * 16;
    const int b_row  = (lane & 7) + (lane >> 4) * 8;
    const int b_koff = ((lane >> 3) & 1) * 16;

    float acc[2][8][4];
    #pragma unroll
    for (int i = 0; i < 2; ++i)
        #pragma unroll
        for (int j = 0; j < 8; ++j)
            #pragma unroll
            for (int q = 0; q < 4; ++q) acc[i][j][q] = 0.f;

    const size_t wko = (size_t)k * 128 * CIN;

    const int r0 = t >> 2, j0 = t & 3;
    const int r1 = 64 + r0;
    const size_t a0b = (size_t)sIdx[r0] * CIN;
    const size_t a1b = (size_t)sIdx[r1] * CIN;
    const size_t b0b = wko + (size_t)r0 * CIN;
    const size_t b1b = wko + (size_t)r1 * CIN;
    const int to0 = r0 * LDB + j0 * 16;
    const int to1 = r1 * LDB + j0 * 16;

    // depth-2 register prefetch: P[slot][tile 0..7]
    uint4 P[2][8];
    #pragma unroll
    for (int sl = 0; sl < 2; ++sl) {
        const int c0 = sl * BK;
        P[sl][0] = *((const uint4*)(shi + a0b + c0) + j0);
        P[sl][1] = *((const uint4*)(slo + a0b + c0) + j0);
        P[sl][2] = *((const uint4*)(whi + b0b + c0) + j0);
        P[sl][3] = *((const uint4*)(wlo + b0b + c0) + j0);
        P[sl][4] = *((const uint4*)(shi + a1b + c0) + j0);
        P[sl][5] = *((const uint4*)(slo + a1b + c0) + j0);
        P[sl][6] = *((const uint4*)(whi + b1b + c0) + j0);
        P[sl][7] = *((const uint4*)(wlo + b1b + c0) + j0);
    }

    #pragma unroll
    for (int ch = 0; ch < NCH; ++ch) {
        const int sl = ch & 1;
        *(uint4*)((char*)Ahi + to0) = P[sl][0];
        *(uint4*)((char*)Alo + to0) = P[sl][1];
        *(uint4*)((char*)Bhi + to0) = P[sl][2];
        *(uint4*)((char*)Blo + to0) = P[sl][3];
        *(uint4*)((char*)Ahi + to1) = P[sl][4];
        *(uint4*)((char*)Alo + to1) = P[sl][5];
        *(uint4*)((char*)Bhi + to1) = P[sl][6];
        *(uint4*)((char*)Blo + to1) = P[sl][7];
        __syncthreads();

        if (ch + 2 < NCH) {
            const int c0 = (ch + 2) * BK;
            P[sl][0] = *((const uint4*)(shi + a0b + c0) + j0);
            P[sl][1] = *((const uint4*)(slo + a0b + c0) + j0);
            P[sl][2] = *((const uint4*)(whi + b0b + c0) + j0);
            P[sl][3] = *((const uint4*)(wlo + b0b + c0) + j0);
            P[sl][4] = *((const uint4*)(shi + a1b + c0) + j0);
            P[sl][5] = *((const uint4*)(slo + a1b + c0) + j0);
            P[sl][6] = *((const uint4*)(whi + b1b + c0) + j0);
            P[sl][7] = *((const uint4*)(wlo + b1b + c0) + j0);
        }

        #pragma unroll
        for (int ks = 0; ks < BK / 16; ++ks) {
            const int akb = ks * 32 + a_koff;
            const int bkb = ks * 32 + b_koff;
            unsigned ah[2][4], al[2][4];
            #pragma unroll
            for (int mt = 0; mt < 2; ++mt) {
                unsigned aoff = (unsigned)((wm + mt * 16 + a_row) * LDB + akb);
                ldsm4(ah[mt], uAhi + aoff);
                ldsm4(al[mt], uAlo + aoff);
            }
            #pragma unroll
            for (int n2 = 0; n2 < 4; ++n2) {
                unsigned boff = (unsigned)((wn + n2 * 16 + b_row) * LDB + bkb);
                unsigned bh[4], bl[4];
                ldsm4(bh, uBhi + boff);
                ldsm4(bl, uBlo + boff);
                #pragma unroll
                for (int mt = 0; mt < 2; ++mt) {
                    mma16816(acc[mt][n2 * 2],     ah[mt], bh);
                    mma16816(acc[mt][n2 * 2],     ah[mt], bl);
                    mma16816(acc[mt][n2 * 2],     al[mt], bh);
                    mma16816(acc[mt][n2 * 2 + 1], ah[mt], bh + 2);
                    mma16816(acc[mt][n2 * 2 + 1], ah[mt], bl + 2);
                    mma16816(acc[mt][n2 * 2 + 1], al[mt], bh + 2);
                }
            }
        }
        __syncthreads();
    }

    // ---- epilogue: smem transpose -> coalesced red.v4 scatter ----
    const int myp = (warp & 3) >> 1;
    const int cq = tid * 2;
    #pragma unroll
    for (int p = 0; p < 2; ++p) {
        if (myp == p) {
            #pragma unroll
            for (int mt = 0; mt < 2; ++mt)
                #pragma unroll
                for (int half = 0; half < 2; ++half) {
                    int lrow = (wm & 63) + mt * 16 + g + half * 8;
                    #pragma unroll
                    for (int na = 0; na < 8; ++na) {
                        int col = wn + na * 8 + cq;
                        *(float2*)&T[lrow * 132 + col] =
                            make_float2(acc[mt][na][half * 2],
                                        acc[mt][na][half * 2 + 1]);
                    }
                }
        }
        __syncthreads();
        #pragma unroll
        for (int i = 0; i < 8; ++i) {
            int lrow = i * 8 + warp;
            int cpos = lane * 4;
            int orow = sOut[p * 64 + lrow];
            if (orow >= 0) {
                float4 v = *(const float4*)&T[lrow * 132 + cpos];
                red_v4(dstbase + (size_t)orow * kCO + cpos, v);
            }
        }
        __syncthreads();
    }
}

// ---------------- skip GEMM: K-split 4, red.v4 accumulate into g_skip --------
// grid = 4 (K-splits) x 128 (row tiles of 16); bias applied in out_ep.
__global__ void __launch_bounds__(256)
skip_kernel(const float* __restrict__ feats,
            const float* __restrict__ w)
{
    constexpr int TM = 16, TK = 32;
    __shared__ float Ws[TK * 128];
    __shared__ float Gs[TK][TM + 1];
    const int ksp = blockIdx.x >> 7;              // 0..3
    const int m0 = (blockIdx.x & 127) * TM;
    const int t = threadIdx.x;

    float acc[8];
    #pragma unroll
    for (int j = 0; j < 8; ++j) acc[j] = 0.f;

    const int tr = t >> 4;
    const int tc = (t & 15) << 3;
    const int cbase = ksp * 64;

    #pragma unroll
    for (int cc = 0; cc < 2; ++cc) {
        const int c0 = cbase + cc * TK;
        {
            const float4* wsrc = (const float4*)(w + c0 * 128);
            float4* wdst = (float4*)Ws;
            #pragma unroll
            for (int i = 0; i < 4; ++i)
                wdst[t + i * 256] = wsrc[t + i * 256];
        }
        {
            const int c = t & 31;
            #pragma unroll
            for (int i = 0; i < 2; ++i) {
                int r = (t >> 5) + i * 8;
                Gs[c][r] = feats[(size_t)(m0 + r) * kC + c0 + c];
            }
        }
        __syncthreads();
        #pragma unroll
        for (int kk = 0; kk < TK; ++kk) {
            float a0 = Gs[kk][tr];
            float4 b0 = *(const float4*)&Ws[kk * 128 + tc];
            float4 b1 = *(const float4*)&Ws[kk * 128 + tc + 4];
            float bv[8] = {b0.x, b0.y, b0.z, b0.w, b1.x, b1.y, b1.z, b1.w};
            #pragma unroll
            for (int j = 0; j < 8; ++j)
                acc[j] = fmaf(a0, bv[j], acc[j]);
        }
        __syncthreads();
    }
    int m = m0 + tr;
    red_v4(&g_skip[(size_t)m * kCO + tc],
           make_float4(acc[0], acc[1], acc[2], acc[3]));
    red_v4(&g_skip[(size_t)m * kCO + tc + 4],
           make_float4(acc[4], acc[5], acc[6], acc[7]));
}

// ---------------- h1 epilogue: +bias -> LN -> SiLU -> bf16 hi/lo -------------
__global__ void h1_ep_kernel(const float* __restrict__ c1b) {
    const int m = blockIdx.x, t = threadIdx.x;   // 128
    const int wid = t >> 5, lane = t & 31;
    __shared__ float red[4];
    float x = g_h1acc[m * kCO + t] + c1b[t];
    float s = x;
    #pragma unroll
    for (int o = 16; o; o >>= 1) s += __shfl_xor_sync(0xffffffffu, s, o);
    if (lane == 0) red[wid] = s;
    __syncthreads();
    const float mean = (red[0] + red[1] + red[2] + red[3]) * (1.f / kCO);
    const float d = x - mean;
    float s2 = d * d;
    #pragma unroll
    for (int o = 16; o; o >>= 1) s2 += __shfl_xor_sync(0xffffffffu, s2, o);
    __syncthreads();
    if (lane == 0) red[wid] = s2;
    __syncthreads();
    const float var = (red[0] + red[1] + red[2] + red[3]) * (1.f / kCO);
    const float y = d * rsqrtf(var + 1e-6f);
    const float h = y / (1.f + expf(-y));
    __nv_bfloat16 hh = __float2bfloat16(h);
    g_h1hi[m * kCO + t] = hh;
    g_h1lo[m * kCO + t] = __float2bfloat16(h - __bfloat162float(hh));
}

// ---------------- out epilogue: += c2 bias + skip + skip bias (active rows) --
__global__ void out_ep_kernel(float* __restrict__ out,
                              const float* __restrict__ c2b,
                              const float* __restrict__ skb) {
    if ((int)blockIdx.x >= g_cnt) return;
    const int m = g_list[blockIdx.x], t = threadIdx.x;   // 128
    out[(size_t)m * kCO + t] += c2b[t] + skb[t] + g_skip[(size_t)(m >> 3) * kCO + t];
}

// ---------------- launch (ONLY harness pointers cross the boundary) ----------
extern "C" void kernel_launch(void* const* d_in, const int* in_sizes, int n_in,
                              void* d_out, int out_size)
{
    const float* feats = (const float*)d_in[0];
    const float* n1w   = (const float*)d_in[1];
    const float* n1b   = (const float*)d_in[2];
    const float* sdw   = (const float*)d_in[3];
    const float* sdb   = (const float*)d_in[4];
    const float* c1w   = (const float*)d_in[5];
    const float* c1b   = (const float*)d_in[6];
    const float* c2w   = (const float*)d_in[7];
    const float* c2b   = (const float*)d_in[8];
    const float* skw   = (const float*)d_in[9];
    const float* skb   = (const float*)d_in[10];
    const int*   coords= (const int*)d_in[11];

    float* out        = (float*)d_out;
    float* subdiv_out = out + (size_t)kM * kCO;

    prep_kernel<<<PREP_BLOCKS, 256>>>(out, c1w, c2w);
    scatter_kernel<<<kM / 256, 256>>>(coords);        // MUST follow sentinel fill
    row_kernel<<<kN, 256>>>(feats, n1w, n1b, sdw, sdb, subdiv_out);
    skip_kernel<<<4 * 128, 256>>>(feats, skw);        // after prep zeroes g_skip
    nidx_kernel<<<dim3(kM / 256, 9), 256>>>(coords);
    tap_fill_kernel<<<54, 256>>>();
    tapgemm_mma<1><<<27 * 128, 256>>>(nullptr);
    h1_ep_kernel<<<kM, 128>>>(c1b);
    tapgemm_mma<2><<<27 * 128, 256>>>(out);
    out_ep_kernel<<<kM, 128>>>(out, c2b, skb);
}

// round 13
// speedup vs baseline: 1.0418x; 1.0418x over previous
#include <cuda_runtime.h>
#include <cuda_bf16.h>
#include <math.h>

// ---------------- problem constants ----------------
constexpr int kN  = 2048;
constexpr int kC  = 256;
constexpr int kCO = 128;
constexpr int kM  = 8 * kN;      // 16384
constexpr int kG  = 66;
constexpr int kG3 = kG * kG * kG;

// ---------------- scratch globals (NEVER passed as kernel args from host) ----
__device__ __nv_bfloat16 g_hhi [(kN + 1) * kC];
__device__ __nv_bfloat16 g_hlo [(kN + 1) * kC];
__device__ __nv_bfloat16 g_h1hi[(kM + 1) * kCO];
__device__ __nv_bfloat16 g_h1lo[(kM + 1) * kCO];
__device__ float g_h1acc[kM * kCO];
__device__ float g_skip [kN * kCO];
__device__ int   g_grid[kG3];
__device__ int   g_nidx [kM * 27];
__device__ int   g_nidx1[kM * 27];
__device__ int   g_mask[kM];
__device__ int   g_cnt;
__device__ int   g_list[kM];
__device__ int   g_in1 [kM * 27 + 27 * 128], g_out1[kM * 27 + 27 * 128];
__device__ int   g_in2 [kM * 27 + 27 * 128], g_out2[kM * 27 + 27 * 128];
__device__ int   g_cnt1[27], g_start1[27], g_plen1[27];
__device__ int   g_cnt2[27], g_start2[27], g_plen2[27];
// transposed bf16 weights: [27][128(n)][CIN(c)]
__device__ __nv_bfloat16 g_w1hi[27 * 128 * kC],  g_w1lo[27 * 128 * kC];
__device__ __nv_bfloat16 g_w2hi[27 * 128 * kCO], g_w2lo[27 * 128 * kCO];

// ---------------- ptx helpers ----------------
__device__ __forceinline__ unsigned smem_u32(const void* p) {
    unsigned a;
    asm("{ .reg .u64 t; cvta.to.shared.u64 t, %1; cvt.u32.u64 %0, t; }"
        : "=r"(a) : "l"(p));
    return a;
}
__device__ __forceinline__ void ldsm4(unsigned* r, unsigned addr) {
    asm volatile("ldmatrix.sync.aligned.m8n8.x4.shared.b16 {%0,%1,%2,%3}, [%4];"
                 : "=r"(r[0]), "=r"(r[1]), "=r"(r[2]), "=r"(r[3]) : "r"(addr));
}
__device__ __forceinline__ void mma16816(float* d, const unsigned* a,
                                         const unsigned* b) {
    asm volatile(
        "mma.sync.aligned.m16n8k16.row.col.f32.bf16.bf16.f32 "
        "{%0,%1,%2,%3}, {%4,%5,%6,%7}, {%8,%9}, {%0,%1,%2,%3};"
        : "+f"(d[0]), "+f"(d[1]), "+f"(d[2]), "+f"(d[3])
        : "r"(a[0]), "r"(a[1]), "r"(a[2]), "r"(a[3]), "r"(b[0]), "r"(b[1]));
}
__device__ __forceinline__ void red_v4(float* p, float4 v) {
    asm volatile("red.global.add.v4.f32 [%0], {%1, %2, %3, %4};"
                 :: "l"(p), "f"(v.x), "f"(v.y), "f"(v.z), "f"(v.w) : "memory");
}

// ---------------- fused prep: zero + coalesced weight transpose + grid -------
// NOTE: the child->grid scatter is a SEPARATE subsequent launch; a sentinel
// write racing a scatter write within one launch silently drops voxels.
constexpr int PB0 = (kM * kCO) / 256;          // 8192  zero h1acc/out
constexpr int PBS = (kN * kCO) / 256;          // 1024  zero g_skip
constexpr int PT1 = 27 * 8 * 4;                // 864   w1 32x32 transpose tiles
constexpr int PT2 = 27 * 4 * 4;                // 432   w2 tiles
constexpr int PB3 = (kG3 + 255) / 256;         // 1124  grid sentinel
constexpr int PREP_BLOCKS = PB0 + PBS + PT1 + PT2 + PB3 + 1;

__global__ void prep_kernel(float* __restrict__ out,
                            const float* __restrict__ c1w,
                            const float* __restrict__ c2w) {
    __shared__ float sT[32][33];
    const int b = blockIdx.x, t = threadIdx.x;
    if (b < PB0) {
        int i = b * 256 + t;
        g_h1acc[i] = 0.f;
        out[i] = 0.f;
    } else if (b < PB0 + PBS) {
        g_skip[(b - PB0) * 256 + t] = 0.f;
    } else if (b < PB0 + PBS + PT1) {
        // w1: [27][256(c)][128(n)] -> [27][128(n)][256(c)], 32x32 tiles
        int b1 = b - PB0 - PBS;
        int k = b1 >> 5, r = b1 & 31;
        int c0 = (r >> 2) * 32, n0 = (r & 3) * 32;
        const float* wk = c1w + (size_t)k * kC * 128;
        int nx = t & 31, cy = t >> 5;
        #pragma unroll
        for (int i = 0; i < 4; ++i)
            sT[cy + 8 * i][nx] = wk[(size_t)(c0 + cy + 8 * i) * 128 + n0 + nx];
        __syncthreads();
        int cx = t & 31, ny = t >> 5;
        #pragma unroll
        for (int i = 0; i < 4; ++i) {
            float v = sT[cx][ny + 8 * i];
            __nv_bfloat16 h = __float2bfloat16(v);
            size_t o = (size_t)k * 128 * kC + (size_t)(n0 + ny + 8 * i) * kC + c0 + cx;
            g_w1hi[o] = h;
            g_w1lo[o] = __float2bfloat16(v - __bfloat162float(h));
        }
    } else if (b < PB0 + PBS + PT1 + PT2) {
        // w2: [27][128(c)][128(n)] -> [27][128(n)][128(c)]
        int b2 = b - PB0 - PBS - PT1;
        int k = b2 >> 4, r = b2 & 15;
        int c0 = (r >> 2) * 32, n0 = (r & 3) * 32;
        const float* wk = c2w + (size_t)k * kCO * 128;
        int nx = t & 31, cy = t >> 5;
        #pragma unroll
        for (int i = 0; i < 4; ++i)
            sT[cy + 8 * i][nx] = wk[(size_t)(c0 + cy + 8 * i) * 128 + n0 + nx];
        __syncthreads();
        int cx = t & 31, ny = t >> 5;
        #pragma unroll
        for (int i = 0; i < 4; ++i) {
            float v = sT[cx][ny + 8 * i];
            __nv_bfloat16 h = __float2bfloat16(v);
            size_t o = (size_t)k * 128 * kCO + (size_t)(n0 + ny + 8 * i) * kCO + c0 + cx;
            g_w2hi[o] = h;
            g_w2lo[o] = __float2bfloat16(v - __bfloat162float(h));
        }
    } else if (b < PB0 + PBS + PT1 + PT2 + PB3) {
        int i = (b - PB0 - PBS - PT1 - PT2) * 256 + t;
        if (i < kG3) g_grid[i] = kM;
    } else {
        if (t < kC)  { g_hhi[kN * kC + t] = __float2bfloat16(0.f);
                       g_hlo[kN * kC + t] = __float2bfloat16(0.f); }
        if (t < kCO) { g_h1hi[kM * kCO + t] = __float2bfloat16(0.f);
                       g_h1lo[kM * kCO + t] = __float2bfloat16(0.f); }
        if (t == 0)  g_cnt = 0;
        if (t < 27)  { g_cnt1[t] = 0; g_cnt2[t] = 0; }
    }
}

// ---------------- child scatter (separate launch: ordered AFTER sentinel) ----
__global__ void scatter_kernel(const int* __restrict__ coords) {
    int m = blockIdx.x * 256 + threadIdx.x;
    int n = m >> 3, j = m & 7;
    int cx = coords[n * 3 + 0] * 2 + ((j >> 2) & 1);
    int cy = coords[n * 3 + 1] * 2 + ((j >> 1) & 1);
    int cz = coords[n * 3 + 2] * 2 + (j & 1);
    g_grid[((cx + 1) * kG + (cy + 1)) * kG + (cz + 1)] = m;
}

// ---------------- per-parent: subdiv + mask + compact + LN + SiLU ------------
__global__ void row_kernel(const float* __restrict__ feats,
                           const float* __restrict__ n1w,
                           const float* __restrict__ n1b,
                           const float* __restrict__ sdw,
                           const float* __restrict__ sdb,
                           float* __restrict__ subdiv_out) {
    const int n = blockIdx.x;
    const int t = threadIdx.x;           // 256
    const int wid = t >> 5, lane = t & 31;
    __shared__ float sf[kC];
    __shared__ float red[8];
    __shared__ int   s_act[8];

    float x = feats[n * kC + t];
    sf[t] = x;
    __syncthreads();

    {
        float p = 0.f;
        #pragma unroll
        for (int i = 0; i < 8; ++i) {
            int c = lane + i * 32;
            p += sf[c] * sdw[c * 8 + wid];
        }
        #pragma unroll
        for (int o = 16; o; o >>= 1) p += __shfl_xor_sync(0xffffffffu, p, o);
        if (lane == 0) {
            p += sdb[wid];
            subdiv_out[n * 8 + wid] = p;
            int act = (p > 0.f) ? 1 : 0;
            g_mask[n * 8 + wid] = act;
            s_act[wid] = act;
        }
    }

    float s = x;
    #pragma unroll
    for (int o = 16; o; o >>= 1) s += __shfl_xor_sync(0xffffffffu, s, o);
    if (lane == 0) red[wid] = s;
    __syncthreads();

    if (wid == 0) {
        bool act = (lane < 8) && (s_act[lane] != 0);
        unsigned ball = __ballot_sync(0xffffffffu, act);
        int c = __popc(ball);
        int base = 0;
        if (lane == 0 && c) base = atomicAdd(&g_cnt, c);
        base = __shfl_sync(0xffffffffu, base, 0);
        if (act) g_list[base + __popc(ball & ((1u << lane) - 1u))] = n * 8 + lane;
    }

    float tot = 0.f;
    #pragma unroll
    for (int i = 0; i < 8; ++i) tot += red[i];
    const float mean = tot * (1.f / kC);
    const float d = x - mean;
    float s2 = d * d;
    #pragma unroll
    for (int o = 16; o; o >>= 1) s2 += __shfl_xor_sync(0xffffffffu, s2, o);
    __syncthreads();
    if (lane == 0) red[wid] = s2;
    __syncthreads();
    float vtot = 0.f;
    #pragma unroll
    for (int i = 0; i < 8; ++i) vtot += red[i];
    const float var = vtot * (1.f / kC);
    const float y = d * rsqrtf(var + 1e-6f) * n1w[t] + n1b[t];
    const float h = y / (1.f + expf(-y));
    __nv_bfloat16 hh = __float2bfloat16(h);
    g_hhi[n * kC + t] = hh;
    g_hlo[n * kC + t] = __float2bfloat16(h - __bfloat162float(hh));
}

// ---------------- neighbor table + fused tap counting (64 x 9 blocks) --------
__global__ void nidx_kernel(const int* __restrict__ coords) {
    __shared__ int c1[3], c2[3];
    const int t = threadIdx.x;
    const int lane = t & 31;
    const int k0 = blockIdx.y * 3;
    if (t < 3) { c1[t] = 0; c2[t] = 0; }
    __syncthreads();

    int m = blockIdx.x * 256 + t;
    int n = m >> 3, j = m & 7;
    int gx = coords[n * 3 + 0] * 2 + ((j >> 2) & 1) + 1;
    int gy = coords[n * 3 + 1] * 2 + ((j >> 1) & 1) + 1;
    int gz = coords[n * 3 + 2] * 2 + (j & 1) + 1;
    const int msk = g_mask[m];
    #pragma unroll
    for (int kk = 0; kk < 3; ++kk) {
        int k = k0 + kk;
        int dx = k / 9 - 1, dy = (k / 3) % 3 - 1, dz = k % 3 - 1;
        int nb = g_grid[((gx + dx) * kG + (gy + dy)) * kG + (gz + dz)];
        g_nidx[m * 27 + k] = nb;
        int in1 = (nb == kM) ? kN : (g_mask[nb] ? (nb >> 3) : kN);
        g_nidx1[m * 27 + k] = in1;
        unsigned b1 = __ballot_sync(0xffffffffu, in1 != kN);
        unsigned b2 = __ballot_sync(0xffffffffu, msk && (nb != kM));
        if (lane == 0) {
            if (b1) atomicAdd(&c1[kk], __popc(b1));
            if (b2) atomicAdd(&c2[kk], __popc(b2));
        }
    }
    __syncthreads();
    if (t < 3) {
        if (c1[t]) atomicAdd(&g_cnt1[k0 + t], c1[t]);
        if (c2[t]) atomicAdd(&g_cnt2[k0 + t], c2[t]);
    }
}

// ---------------- scan: starts + padded lengths ----------------
__global__ void tap_scan_kernel() {
    if (threadIdx.x != 0) return;
    int s1 = 0, s2 = 0;
    for (int k = 0; k < 27; ++k) {
        int c = g_cnt1[k], p = (c + 127) & ~127;
        g_start1[k] = s1; g_plen1[k] = p; s1 += p;
        c = g_cnt2[k]; p = (c + 127) & ~127;
        g_start2[k] = s2; g_plen2[k] = p; s2 += p;
    }
}

// ---------------- fill both pair lists in one launch (54 blocks) -------------
__device__ __forceinline__ bool tap_flag_rt(int mode, int m, int k, int& in_id) {
    if (mode == 1) {
        in_id = g_nidx1[m * 27 + k];
        return in_id != kN;
    } else {
        in_id = g_nidx[m * 27 + k];
        return g_mask[m] && (in_id != kM);
    }
}

__global__ void tap_fill_kernel() {
    const int mode = (blockIdx.x < 27) ? 1 : 2;
    const int k = blockIdx.x % 27;
    const int t = threadIdx.x;
    int* __restrict__ pin  = (mode == 1) ? g_in1  : g_in2;
    int* __restrict__ pout = (mode == 1) ? g_out1 : g_out2;
    const int start = (mode == 1 ? g_start1 : g_start2)[k];

    int cnt = 0;
    #pragma unroll 4
    for (int r = 0; r < 64; ++r) {
        int in_id;
        if (tap_flag_rt(mode, t * 64 + r, k, in_id)) ++cnt;
    }
    // Hillis-Steele inclusive scan over 256 counts
    __shared__ int sh[256];
    sh[t] = cnt;
    __syncthreads();
    #pragma unroll
    for (int off = 1; off < 256; off <<= 1) {
        int u = (t >= off) ? sh[t - off] : 0;
        __syncthreads();
        sh[t] += u;
        __syncthreads();
    }
    int w = start + sh[t] - cnt;      // exclusive prefix
    const int tot = sh[255];
    for (int r = 0; r < 64; ++r) {
        int m = t * 64 + r, in_id;
        if (tap_flag_rt(mode, m, k, in_id)) {
            pin[w] = in_id;
            pout[w] = m;
            ++w;
        }
    }
    const int plen = (mode == 1 ? g_plen1 : g_plen2)[k];
    for (int i = tot + t; i < plen; i += 256) {
        pin[start + i] = (mode == 1) ? kN : kM;   // zero bf16 rows
        pout[start + i] = -1;
    }
}

// ---------------- tensor-core tap GEMM via mma.sync + ldmatrix ---------------
// Block tile M=128 x N=128, BK=32, 256 threads (8 warps as 4x2, warp 32x64).
// Depth-2 register prefetch, ldmatrix.x4 fragments, smem-transposed red.v4
// scatter. Globals selected via MODE template.
template <int MODE>
__global__ void __launch_bounds__(256)
tapgemm_mma(float* __restrict__ ext_out)
{
    constexpr int CIN = (MODE == 1) ? kC : kCO;
    constexpr int BK  = 32;
    constexpr int NCH = CIN / BK;
    constexpr int LDB = 80;                 // tile row stride in bytes (40 bf16)

    // 4 bf16 tiles (40960B) aliased with the fp32 transpose buffer (33792B)
    __shared__ __align__(16) char smem_raw[40960];
    __shared__ int sIdx[128], sOut[128];
    __nv_bfloat16* Ahi = (__nv_bfloat16*)(smem_raw);
    __nv_bfloat16* Alo = (__nv_bfloat16*)(smem_raw + 10240);
    __nv_bfloat16* Bhi = (__nv_bfloat16*)(smem_raw + 20480);
    __nv_bfloat16* Blo = (__nv_bfloat16*)(smem_raw + 30720);
    float* T = (float*)smem_raw;            // 64 x 132 floats

    const int k = blockIdx.x >> 7;
    const int s = blockIdx.x & 127;
    const int plen = (MODE == 1 ? g_plen1 : g_plen2)[k];
    if (s * 128 >= plen) return;
    const int base = (MODE == 1 ? g_start1 : g_start2)[k] + s * 128;

    const __nv_bfloat16* __restrict__ shi = (MODE == 1) ? g_hhi : g_h1hi;
    const __nv_bfloat16* __restrict__ slo = (MODE == 1) ? g_hlo : g_h1lo;
    const __nv_bfloat16* __restrict__ whi = (MODE == 1) ? g_w1hi : g_w2hi;
    const __nv_bfloat16* __restrict__ wlo = (MODE == 1) ? g_w1lo : g_w2lo;
    const int* __restrict__ pin  = (MODE == 1) ? g_in1  : g_in2;
    const int* __restrict__ pout = (MODE == 1) ? g_out1 : g_out2;
    float* __restrict__ dstbase  = (MODE == 1) ? g_h1acc : ext_out;

    const int t = threadIdx.x;
    if (t < 128) {
        sIdx[t] = pin[base + t];
        sOut[t] = pout[base + t];
    }
    __syncthreads();

    const unsigned uAhi = smem_u32(Ahi), uAlo = smem_u32(Alo);
    const unsigned uBhi = smem_u32(Bhi), uBlo = smem_u32(Blo);

    const int warp = t >> 5, lane = t & 31;
    const int g = lane >> 2, tid = lane & 3;
    const int wm = (warp & 3) * 32;    // m offset
    const int wn = (warp >> 2) * 64;   // n offset

    // ldmatrix lane addressing (PTX x4 spec)
    const int a_row  = lane & 15;
    const int a_koff = (lane >> 4) * 16;
    const int b_row  = (lane & 7) + (lane >> 4) * 8;
    const int b_koff = ((lane >> 3) & 1) * 16;

    float acc[2][8][4];
    #pragma unroll
    for (int i = 0; i < 2; ++i)
        #pragma unroll
        for (int j = 0; j < 8; ++j)
            #pragma unroll
            for (int q = 0; q < 4; ++q) acc[i][j][q] = 0.f;

    const size_t wko = (size_t)k * 128 * CIN;

    const int r0 = t >> 2, j0 = t & 3;
    const int r1 = 64 + r0;
    const size_t a0b = (size_t)sIdx[r0] * CIN;
    const size_t a1b = (size_t)sIdx[r1] * CIN;
    const size_t b0b = wko + (size_t)r0 * CIN;
    const size_t b1b = wko + (size_t)r1 * CIN;
    const int to0 = r0 * LDB + j0 * 16;
    const int to1 = r1 * LDB + j0 * 16;

    // depth-2 register prefetch: P[slot][tile 0..7]
    uint4 P[2][8];
    #pragma unroll
    for (int sl = 0; sl < 2; ++sl) {
        const int c0 = sl * BK;
        P[sl][0] = *((const uint4*)(shi + a0b + c0) + j0);
        P[sl][1] = *((const uint4*)(slo + a0b + c0) + j0);
        P[sl][2] = *((const uint4*)(whi + b0b + c0) + j0);
        P[sl][3] = *((const uint4*)(wlo + b0b + c0) + j0);
        P[sl][4] = *((const uint4*)(shi + a1b + c0) + j0);
        P[sl][5] = *((const uint4*)(slo + a1b + c0) + j0);
        P[sl][6] = *((const uint4*)(whi + b1b + c0) + j0);
        P[sl][7] = *((const uint4*)(wlo + b1b + c0) + j0);
    }

    #pragma unroll
    for (int ch = 0; ch < NCH; ++ch) {
        const int sl = ch & 1;
        *(uint4*)((char*)Ahi + to0) = P[sl][0];
        *(uint4*)((char*)Alo + to0) = P[sl][1];
        *(uint4*)((char*)Bhi + to0) = P[sl][2];
        *(uint4*)((char*)Blo + to0) = P[sl][3];
        *(uint4*)((char*)Ahi + to1) = P[sl][4];
        *(uint4*)((char*)Alo + to1) = P[sl][5];
        *(uint4*)((char*)Bhi + to1) = P[sl][6];
        *(uint4*)((char*)Blo + to1) = P[sl][7];
        __syncthreads();

        if (ch + 2 < NCH) {
            const int c0 = (ch + 2) * BK;
            P[sl][0] = *((const uint4*)(shi + a0b + c0) + j0);
            P[sl][1] = *((const uint4*)(slo + a0b + c0) + j0);
            P[sl][2] = *((const uint4*)(whi + b0b + c0) + j0);
            P[sl][3] = *((const uint4*)(wlo + b0b + c0) + j0);
            P[sl][4] = *((const uint4*)(shi + a1b + c0) + j0);
            P[sl][5] = *((const uint4*)(slo + a1b + c0) + j0);
            P[sl][6] = *((const uint4*)(whi + b1b + c0) + j0);
            P[sl][7] = *((const uint4*)(wlo + b1b + c0) + j0);
        }

        #pragma unroll
        for (int ks = 0; ks < BK / 16; ++ks) {
            const int akb = ks * 32 + a_koff;
            const int bkb = ks * 32 + b_koff;
            unsigned ah[2][4], al[2][4];
            #pragma unroll
            for (int mt = 0; mt < 2; ++mt) {
                unsigned aoff = (unsigned)((wm + mt * 16 + a_row) * LDB + akb);
                ldsm4(ah[mt], uAhi + aoff);
                ldsm4(al[mt], uAlo + aoff);
            }
            #pragma unroll
            for (int n2 = 0; n2 < 4; ++n2) {
                unsigned boff = (unsigned)((wn + n2 * 16 + b_row) * LDB + bkb);
                unsigned bh[4], bl[4];
                ldsm4(bh, uBhi + boff);
                ldsm4(bl, uBlo + boff);
                #pragma unroll
                for (int mt = 0; mt < 2; ++mt) {
                    mma16816(acc[mt][n2 * 2],     ah[mt], bh);
                    mma16816(acc[mt][n2 * 2],     ah[mt], bl);
                    mma16816(acc[mt][n2 * 2],     al[mt], bh);
                    mma16816(acc[mt][n2 * 2 + 1], ah[mt], bh + 2);
                    mma16816(acc[mt][n2 * 2 + 1], ah[mt], bl + 2);
                    mma16816(acc[mt][n2 * 2 + 1], al[mt], bh + 2);
                }
            }
        }
        __syncthreads();
    }

    // ---- epilogue: smem transpose -> coalesced red.v4 scatter ----
    const int myp = (warp & 3) >> 1;
    const int cq = tid * 2;
    #pragma unroll
    for (int p = 0; p < 2; ++p) {
        if (myp == p) {
            #pragma unroll
            for (int mt = 0; mt < 2; ++mt)
                #pragma unroll
                for (int half = 0; half < 2; ++half) {
                    int lrow = (wm & 63) + mt * 16 + g + half * 8;
                    #pragma unroll
                    for (int na = 0; na < 8; ++na) {
                        int col = wn + na * 8 + cq;
                        *(float2*)&T[lrow * 132 + col] =
                            make_float2(acc[mt][na][half * 2],
                                        acc[mt][na][half * 2 + 1]);
                    }
                }
        }
        __syncthreads();
        #pragma unroll
        for (int i = 0; i < 8; ++i) {
            int lrow = i * 8 + warp;
            int cpos = lane * 4;
            int orow = sOut[p * 64 + lrow];
            if (orow >= 0) {
                float4 v = *(const float4*)&T[lrow * 132 + cpos];
                red_v4(dstbase + (size_t)orow * kCO + cpos, v);
            }
        }
        __syncthreads();
    }
}

// ---------------- skip GEMM: K-split 8, red.v4 accumulate into g_skip --------
// grid = 8 (K-splits) x 128 (row tiles of 16); ONE chunk per block, no chain.
// Bias applied in out_ep.
__global__ void __launch_bounds__(256)
skip_kernel(const float* __restrict__ feats,
            const float* __restrict__ w)
{
    constexpr int TM = 16, TK = 32;
    __shared__ float Ws[TK * 128];
    __shared__ float Gs[TK][TM + 1];
    const int ksp = blockIdx.x >> 7;              // 0..7
    const int m0 = (blockIdx.x & 127) * TM;
    const int t = threadIdx.x;

    float acc[8];
    #pragma unroll
    for (int j = 0; j < 8; ++j) acc[j] = 0.f;

    const int tr = t >> 4;
    const int tc = (t & 15) << 3;
    const int c0 = ksp * TK;

    {
        const float4* wsrc = (const float4*)(w + c0 * 128);
        float4* wdst = (float4*)Ws;
        #pragma unroll
        for (int i = 0; i < 4; ++i)
            wdst[t + i * 256] = wsrc[t + i * 256];
    }
    {
        const int c = t & 31;
        #pragma unroll
        for (int i = 0; i < 2; ++i) {
            int r = (t >> 5) + i * 8;
            Gs[c][r] = feats[(size_t)(m0 + r) * kC + c0 + c];
        }
    }
    __syncthreads();
    #pragma unroll
    for (int kk = 0; kk < TK; ++kk) {
        float a0 = Gs[kk][tr];
        float4 b0 = *(const float4*)&Ws[kk * 128 + tc];
        float4 b1 = *(const float4*)&Ws[kk * 128 + tc + 4];
        float bv[8] = {b0.x, b0.y, b0.z, b0.w, b1.x, b1.y, b1.z, b1.w};
        #pragma unroll
        for (int j = 0; j < 8; ++j)
            acc[j] = fmaf(a0, bv[j], acc[j]);
    }
    int m = m0 + tr;
    red_v4(&g_skip[(size_t)m * kCO + tc],
           make_float4(acc[0], acc[1], acc[2], acc[3]));
    red_v4(&g_skip[(size_t)m * kCO + tc + 4],
           make_float4(acc[4], acc[5], acc[6], acc[7]));
}

// ---------------- h1 epilogue: +bias -> LN -> SiLU -> bf16 hi/lo -------------
__global__ void h1_ep_kernel(const float* __restrict__ c1b) {
    const int m = blockIdx.x, t = threadIdx.x;   // 128
    const int wid = t >> 5, lane = t & 31;
    __shared__ float red[4];
    float x = g_h1acc[m * kCO + t] + c1b[t];
    float s = x;
    #pragma unroll
    for (int o = 16; o; o >>= 1) s += __shfl_xor_sync(0xffffffffu, s, o);
    if (lane == 0) red[wid] = s;
    __syncthreads();
    const float mean = (red[0] + red[1] + red[2] + red[3]) * (1.f / kCO);
    const float d = x - mean;
    float s2 = d * d;
    #pragma unroll
    for (int o = 16; o; o >>= 1) s2 += __shfl_xor_sync(0xffffffffu, s2, o);
    __syncthreads();
    if (lane == 0) red[wid] = s2;
    __syncthreads();
    const float var = (red[0] + red[1] + red[2] + red[3]) * (1.f / kCO);
    const float y = d * rsqrtf(var + 1e-6f);
    const float h = y / (1.f + expf(-y));
    __nv_bfloat16 hh = __float2bfloat16(h);
    g_h1hi[m * kCO + t] = hh;
    g_h1lo[m * kCO + t] = __float2bfloat16(h - __bfloat162float(hh));
}

// ---------------- out epilogue: += c2 bias + skip + skip bias (active rows) --
__global__ void out_ep_kernel(float* __restrict__ out,
                              const float* __restrict__ c2b,
                              const float* __restrict__ skb) {
    if ((int)blockIdx.x >= g_cnt) return;
    const int m = g_list[blockIdx.x], t = threadIdx.x;   // 128
    out[(size_t)m * kCO + t] += c2b[t] + skb[t] + g_skip[(size_t)(m >> 3) * kCO + t];
}

// ---------------- launch (ONLY harness pointers cross the boundary) ----------
extern "C" void kernel_launch(void* const* d_in, const int* in_sizes, int n_in,
                              void* d_out, int out_size)
{
    const float* feats = (const float*)d_in[0];
    const float* n1w   = (const float*)d_in[1];
    const float* n1b   = (const float*)d_in[2];
    const float* sdw   = (const float*)d_in[3];
    const float* sdb   = (const float*)d_in[4];
    const float* c1w   = (const float*)d_in[5];
    const float* c1b   = (const float*)d_in[6];
    const float* c2w   = (const float*)d_in[7];
    const float* c2b   = (const float*)d_in[8];
    const float* skw   = (const float*)d_in[9];
    const float* skb   = (const float*)d_in[10];
    const int*   coords= (const int*)d_in[11];

    float* out        = (float*)d_out;
    float* subdiv_out = out + (size_t)kM * kCO;

    prep_kernel<<<PREP_BLOCKS, 256>>>(out, c1w, c2w);
    scatter_kernel<<<kM / 256, 256>>>(coords);        // MUST follow sentinel fill
    row_kernel<<<kN, 256>>>(feats, n1w, n1b, sdw, sdb, subdiv_out);
    skip_kernel<<<8 * 128, 256>>>(feats, skw);        // after prep zeroes g_skip
    nidx_kernel<<<dim3(kM / 256, 9), 256>>>(coords);
    tap_scan_kernel<<<1, 32>>>();
    tap_fill_kernel<<<54, 256>>>();
    tapgemm_mma<1><<<27 * 128, 256>>>(nullptr);
    h1_ep_kernel<<<kM, 128>>>(c1b);
    tapgemm_mma<2><<<27 * 128, 256>>>(out);
    out_ep_kernel<<<kM, 128>>>(out, c2b, skb);
}

// round 14
// speedup vs baseline: 1.1104x; 1.0658x over previous
#include <cuda_runtime.h>
#include <cuda_bf16.h>
#include <math.h>

// ---------------- problem constants ----------------
constexpr int kN  = 2048;
constexpr int kC  = 256;
constexpr int kCO = 128;
constexpr int kM  = 8 * kN;      // 16384
constexpr int kG  = 66;
constexpr int kG3 = kG * kG * kG;
constexpr int kZROW = 2 * kN;    // zero-pad row index in g_hhi/g_hlo

// ---------------- scratch globals (NEVER passed as kernel args from host) ----
// rows [0,kN): silu(LN(feats)); rows [kN,2kN): raw feats; row 2kN: zeros
__device__ __nv_bfloat16 g_hhi [(2 * kN + 1) * kC];
__device__ __nv_bfloat16 g_hlo [(2 * kN + 1) * kC];
__device__ __nv_bfloat16 g_h1hi[(kM + 1) * kCO];
__device__ __nv_bfloat16 g_h1lo[(kM + 1) * kCO];
// rows [0,kM): conv1 accumulator; rows [kM,kM+kN): skip accumulator
__device__ float g_h1acc[(kM + kN) * kCO];
__device__ int   g_grid[kG3];
__device__ int   g_nidx [kM * 27];
__device__ int   g_nidx1[kM * 27];
__device__ int   g_mask[kM];
__device__ int   g_cnt;
__device__ int   g_list[kM];
__device__ int   g_in1 [kM * 27 + 28 * 128 + 2048], g_out1[kM * 27 + 28 * 128 + 2048];
__device__ int   g_in2 [kM * 27 + 27 * 128], g_out2[kM * 27 + 27 * 128];
__device__ int   g_cnt1[28], g_start1[28], g_plen1[28];
__device__ int   g_cnt2[27], g_start2[27], g_plen2[27];
// transposed bf16 weights: w1 has 28 slots ([27] = skip weights)
__device__ __nv_bfloat16 g_w1hi[28 * 128 * kC],  g_w1lo[28 * 128 * kC];
__device__ __nv_bfloat16 g_w2hi[27 * 128 * kCO], g_w2lo[27 * 128 * kCO];

// ---------------- ptx helpers ----------------
__device__ __forceinline__ unsigned smem_u32(const void* p) {
    unsigned a;
    asm("{ .reg .u64 t; cvta.to.shared.u64 t, %1; cvt.u32.u64 %0, t; }"
        : "=r"(a) : "l"(p));
    return a;
}
__device__ __forceinline__ void ldsm4(unsigned* r, unsigned addr) {
    asm volatile("ldmatrix.sync.aligned.m8n8.x4.shared.b16 {%0,%1,%2,%3}, [%4];"
                 : "=r"(r[0]), "=r"(r[1]), "=r"(r[2]), "=r"(r[3]) : "r"(addr));
}
__device__ __forceinline__ void mma16816(float* d, const unsigned* a,
                                         const unsigned* b) {
    asm volatile(
        "mma.sync.aligned.m16n8k16.row.col.f32.bf16.bf16.f32 "
        "{%0,%1,%2,%3}, {%4,%5,%6,%7}, {%8,%9}, {%0,%1,%2,%3};"
        : "+f"(d[0]), "+f"(d[1]), "+f"(d[2]), "+f"(d[3])
        : "r"(a[0]), "r"(a[1]), "r"(a[2]), "r"(a[3]), "r"(b[0]), "r"(b[1]));
}
__device__ __forceinline__ void red_v4(float* p, float4 v) {
    asm volatile("red.global.add.v4.f32 [%0], {%1, %2, %3, %4};"
                 :: "l"(p), "f"(v.x), "f"(v.y), "f"(v.z), "f"(v.w) : "memory");
}

// ---------------- fused prep: zero + coalesced weight transpose + grid -------
// (child->grid scatter is a SEPARATE launch: sentinel/scatter WAW race)
constexpr int PB0 = (kM * kCO) / 256;          // 8192  zero h1acc[0,kM) + out
constexpr int PBS = (kN * kCO) / 256;          // 1024  zero h1acc skip region
constexpr int PT1 = 27 * 8 * 4;                // 864   w1 transpose tiles
constexpr int PTS = 8 * 4;                     // 32    skw transpose tiles
constexpr int PT2 = 27 * 4 * 4;                // 432   w2 tiles
constexpr int PB3 = (kG3 + 255) / 256;         // 1124  grid sentinel
constexpr int PREP_BLOCKS = PB0 + PBS + PT1 + PTS + PT2 + PB3 + 1;

__global__ void prep_kernel(float* __restrict__ out,
                            const float* __restrict__ c1w,
                            const float* __restrict__ c2w,
                            const float* __restrict__ skw) {
    __shared__ float sT[32][33];
    const int b = blockIdx.x, t = threadIdx.x;
    if (b < PB0) {
        int i = b * 256 + t;
        g_h1acc[i] = 0.f;
        out[i] = 0.f;
    } else if (b < PB0 + PBS) {
        g_h1acc[kM * kCO + (b - PB0) * 256 + t] = 0.f;
    } else if (b < PB0 + PBS + PT1 + PTS) {
        // w1 (k<27) and skw (k==27): [CIN(c)][128(n)] -> slot k [128(n)][256(c)]
        int b1 = b - PB0 - PBS;
        int k = b1 >> 5, r = b1 & 31;
        int c0 = (r >> 2) * 32, n0 = (r & 3) * 32;
        const float* wk = (k < 27) ? (c1w + (size_t)k * kC * 128) : skw;
        int nx = t & 31, cy = t >> 5;
        #pragma unroll
        for (int i = 0; i < 4; ++i)
            sT[cy + 8 * i][nx] = wk[(size_t)(c0 + cy + 8 * i) * 128 + n0 + nx];
        __syncthreads();
        int cx = t & 31, ny = t >> 5;
        #pragma unroll
        for (int i = 0; i < 4; ++i) {
            float v = sT[cx][ny + 8 * i];
            __nv_bfloat16 h = __float2bfloat16(v);
            size_t o = (size_t)k * 128 * kC + (size_t)(n0 + ny + 8 * i) * kC + c0 + cx;
            g_w1hi[o] = h;
            g_w1lo[o] = __float2bfloat16(v - __bfloat162float(h));
        }
    } else if (b < PB0 + PBS + PT1 + PTS + PT2) {
        // w2: [27][128(c)][128(n)] -> [27][128(n)][128(c)]
        int b2 = b - PB0 - PBS - PT1 - PTS;
        int k = b2 >> 4, r = b2 & 15;
        int c0 = (r >> 2) * 32, n0 = (r & 3) * 32;
        const float* wk = c2w + (size_t)k * kCO * 128;
        int nx = t & 31, cy = t >> 5;
        #pragma unroll
        for (int i = 0; i < 4; ++i)
            sT[cy + 8 * i][nx] = wk[(size_t)(c0 + cy + 8 * i) * 128 + n0 + nx];
        __syncthreads();
        int cx = t & 31, ny = t >> 5;
        #pragma unroll
        for (int i = 0; i < 4; ++i) {
            float v = sT[cx][ny + 8 * i];
            __nv_bfloat16 h = __float2bfloat16(v);
            size_t o = (size_t)k * 128 * kCO + (size_t)(n0 + ny + 8 * i) * kCO + c0 + cx;
            g_w2hi[o] = h;
            g_w2lo[o] = __float2bfloat16(v - __bfloat162float(h));
        }
    } else if (b < PB0 + PBS + PT1 + PTS + PT2 + PB3) {
        int i = (b - PB0 - PBS - PT1 - PTS - PT2) * 256 + t;
        if (i < kG3) g_grid[i] = kM;
    } else {
        if (t < kC)  { g_hhi[(size_t)kZROW * kC + t] = __float2bfloat16(0.f);
                       g_hlo[(size_t)kZROW * kC + t] = __float2bfloat16(0.f); }
        if (t < kCO) { g_h1hi[kM * kCO + t] = __float2bfloat16(0.f);
                       g_h1lo[kM * kCO + t] = __float2bfloat16(0.f); }
        if (t == 0)  g_cnt = 0;
        if (t < 28)  { g_cnt1[t] = 0; if (t < 27) g_cnt2[t] = 0; }
    }
}

// ---------------- child scatter (separate launch: ordered AFTER sentinel) ----
__global__ void scatter_kernel(const int* __restrict__ coords) {
    int m = blockIdx.x * 256 + threadIdx.x;
    int n = m >> 3, j = m & 7;
    int cx = coords[n * 3 + 0] * 2 + ((j >> 2) & 1);
    int cy = coords[n * 3 + 1] * 2 + ((j >> 1) & 1);
    int cz = coords[n * 3 + 2] * 2 + (j & 1);
    g_grid[((cx + 1) * kG + (cy + 1)) * kG + (cz + 1)] = m;
}

// ---------------- per-parent: subdiv + mask + compact + LN + SiLU ------------
// also stores a bf16 hi/lo split of RAW feats at rows [kN, 2kN)
__global__ void row_kernel(const float* __restrict__ feats,
                           const float* __restrict__ n1w,
                           const float* __restrict__ n1b,
                           const float* __restrict__ sdw,
                           const float* __restrict__ sdb,
                           float* __restrict__ subdiv_out) {
    const int n = blockIdx.x;
    const int t = threadIdx.x;           // 256
    const int wid = t >> 5, lane = t & 31;
    __shared__ float sf[kC];
    __shared__ float red[8];
    __shared__ int   s_act[8];

    float x = feats[n * kC + t];
    sf[t] = x;
    // raw feats split for the fused skip GEMM
    {
        __nv_bfloat16 fh = __float2bfloat16(x);
        g_hhi[(size_t)(kN + n) * kC + t] = fh;
        g_hlo[(size_t)(kN + n) * kC + t] =
            __float2bfloat16(x - __bfloat162float(fh));
    }
    __syncthreads();

    {
        float p = 0.f;
        #pragma unroll
        for (int i = 0; i < 8; ++i) {
            int c = lane + i * 32;
            p += sf[c] * sdw[c * 8 + wid];
        }
        #pragma unroll
        for (int o = 16; o; o >>= 1) p += __shfl_xor_sync(0xffffffffu, p, o);
        if (lane == 0) {
            p += sdb[wid];
            subdiv_out[n * 8 + wid] = p;
            int act = (p > 0.f) ? 1 : 0;
            g_mask[n * 8 + wid] = act;
            s_act[wid] = act;
        }
    }

    float s = x;
    #pragma unroll
    for (int o = 16; o; o >>= 1) s += __shfl_xor_sync(0xffffffffu, s, o);
    if (lane == 0) red[wid] = s;
    __syncthreads();

    if (wid == 0) {
        bool act = (lane < 8) && (s_act[lane] != 0);
        unsigned ball = __ballot_sync(0xffffffffu, act);
        int c = __popc(ball);
        int base = 0;
        if (lane == 0 && c) base = atomicAdd(&g_cnt, c);
        base = __shfl_sync(0xffffffffu, base, 0);
        if (act) g_list[base + __popc(ball & ((1u << lane) - 1u))] = n * 8 + lane;
    }

    float tot = 0.f;
    #pragma unroll
    for (int i = 0; i < 8; ++i) tot += red[i];
    const float mean = tot * (1.f / kC);
    const float d = x - mean;
    float s2 = d * d;
    #pragma unroll
    for (int o = 16; o; o >>= 1) s2 += __shfl_xor_sync(0xffffffffu, s2, o);
    __syncthreads();
    if (lane == 0) red[wid] = s2;
    __syncthreads();
    float vtot = 0.f;
    #pragma unroll
    for (int i = 0; i < 8; ++i) vtot += red[i];
    const float var = vtot * (1.f / kC);
    const float y = d * rsqrtf(var + 1e-6f) * n1w[t] + n1b[t];
    const float h = y / (1.f + expf(-y));
    __nv_bfloat16 hh = __float2bfloat16(h);
    g_hhi[(size_t)n * kC + t] = hh;
    g_hlo[(size_t)n * kC + t] = __float2bfloat16(h - __bfloat162float(hh));
}

// ---------------- neighbor table + fused tap counting (64 x 9 blocks) --------
__global__ void nidx_kernel(const int* __restrict__ coords) {
    __shared__ int c1[3], c2[3];
    const int t = threadIdx.x;
    const int lane = t & 31;
    const int k0 = blockIdx.y * 3;
    if (t < 3) { c1[t] = 0; c2[t] = 0; }
    __syncthreads();

    int m = blockIdx.x * 256 + t;
    int n = m >> 3, j = m & 7;
    int gx = coords[n * 3 + 0] * 2 + ((j >> 2) & 1) + 1;
    int gy = coords[n * 3 + 1] * 2 + ((j >> 1) & 1) + 1;
    int gz = coords[n * 3 + 2] * 2 + (j & 1) + 1;
    const int msk = g_mask[m];
    #pragma unroll
    for (int kk = 0; kk < 3; ++kk) {
        int k = k0 + kk;
        int dx = k / 9 - 1, dy = (k / 3) % 3 - 1, dz = k % 3 - 1;
        int nb = g_grid[((gx + dx) * kG + (gy + dy)) * kG + (gz + dz)];
        g_nidx[m * 27 + k] = nb;
        int in1 = (nb == kM) ? kZROW : (g_mask[nb] ? (nb >> 3) : kZROW);
        g_nidx1[m * 27 + k] = in1;
        unsigned b1 = __ballot_sync(0xffffffffu, in1 != kZROW);
        unsigned b2 = __ballot_sync(0xffffffffu, msk && (nb != kM));
        if (lane == 0) {
            if (b1) atomicAdd(&c1[kk], __popc(b1));
            if (b2) atomicAdd(&c2[kk], __popc(b2));
        }
    }
    __syncthreads();
    if (t < 3) {
        if (c1[t]) atomicAdd(&g_cnt1[k0 + t], c1[t]);
        if (c2[t]) atomicAdd(&g_cnt2[k0 + t], c2[t]);
    }
}

// ---------------- scan: starts + padded lengths (+ dense skip segment 27) ----
__global__ void tap_scan_kernel() {
    if (threadIdx.x != 0) return;
    int s1 = 0, s2 = 0;
    for (int k = 0; k < 27; ++k) {
        int c = g_cnt1[k], p = (c + 127) & ~127;
        g_start1[k] = s1; g_plen1[k] = p; s1 += p;
        c = g_cnt2[k]; p = (c + 127) & ~127;
        g_start2[k] = s2; g_plen2[k] = p; s2 += p;
    }
    g_start1[27] = s1; g_plen1[27] = kN;   // 2048 dense skip pairs
}

// ---------------- fill pair lists (55 blocks: 28 mode1 + 27 mode2) -----------
__device__ __forceinline__ bool tap_flag_rt(int mode, int m, int k, int& in_id) {
    if (mode == 1) {
        in_id = g_nidx1[m * 27 + k];
        return in_id != kZROW;
    } else {
        in_id = g_nidx[m * 27 + k];
        return g_mask[m] && (in_id != kM);
    }
}

__global__ void tap_fill_kernel() {
    const int mode = (blockIdx.x < 28) ? 1 : 2;
    const int k = (mode == 1) ? blockIdx.x : (blockIdx.x - 28);
    const int t = threadIdx.x;
    int* __restrict__ pin  = (mode == 1) ? g_in1  : g_in2;
    int* __restrict__ pout = (mode == 1) ? g_out1 : g_out2;
    const int start = (mode == 1 ? g_start1 : g_start2)[k];

    if (mode == 1 && k == 27) {
        // dense skip segment: in = feats row (kN+n), out = skip acc row (kM+n)
        for (int i = t; i < kN; i += 256) {
            pin[start + i] = kN + i;
            pout[start + i] = kM + i;
        }
        return;
    }

    int cnt = 0;
    #pragma unroll 4
    for (int r = 0; r < 64; ++r) {
        int in_id;
        if (tap_flag_rt(mode, t * 64 + r, k, in_id)) ++cnt;
    }
    __shared__ int sh[256];
    sh[t] = cnt;
    __syncthreads();
    #pragma unroll
    for (int off = 1; off < 256; off <<= 1) {
        int u = (t >= off) ? sh[t - off] : 0;
        __syncthreads();
        sh[t] += u;
        __syncthreads();
    }
    int w = start + sh[t] - cnt;
    const int tot = sh[255];
    for (int r = 0; r < 64; ++r) {
        int m = t * 64 + r, in_id;
        if (tap_flag_rt(mode, m, k, in_id)) {
            pin[w] = in_id;
            pout[w] = m;
            ++w;
        }
    }
    const int plen = (mode == 1 ? g_plen1 : g_plen2)[k];
    for (int i = tot + t; i < plen; i += 256) {
        pin[start + i] = (mode == 1) ? kZROW : kM;   // zero bf16 rows
        pout[start + i] = -1;
    }
}

// ---------------- tensor-core tap GEMM via mma.sync + ldmatrix ---------------
// Block tile M=128 x N=128, BK=32, 256 threads (8 warps as 4x2, warp 32x64).
// Depth-2 register prefetch, ldmatrix.x4 fragments, smem-transposed red.v4
// scatter. MODE1 has 28 segments (27 conv taps + dense skip GEMM).
template <int MODE>
__global__ void __launch_bounds__(256)
tapgemm_mma(float* __restrict__ ext_out)
{
    constexpr int CIN = (MODE == 1) ? kC : kCO;
    constexpr int BK  = 32;
    constexpr int NCH = CIN / BK;
    constexpr int LDB = 80;                 // tile row stride in bytes

    __shared__ __align__(16) char smem_raw[40960];
    __shared__ int sIdx[128], sOut[128];
    __nv_bfloat16* Ahi = (__nv_bfloat16*)(smem_raw);
    __nv_bfloat16* Alo = (__nv_bfloat16*)(smem_raw + 10240);
    __nv_bfloat16* Bhi = (__nv_bfloat16*)(smem_raw + 20480);
    __nv_bfloat16* Blo = (__nv_bfloat16*)(smem_raw + 30720);
    float* T = (float*)smem_raw;            // 64 x 132 floats

    const int k = blockIdx.x >> 7;
    const int s = blockIdx.x & 127;
    const int plen = (MODE == 1 ? g_plen1 : g_plen2)[k];
    if (s * 128 >= plen) return;
    const int base = (MODE == 1 ? g_start1 : g_start2)[k] + s * 128;

    const __nv_bfloat16* __restrict__ shi = (MODE == 1) ? g_hhi : g_h1hi;
    const __nv_bfloat16* __restrict__ slo = (MODE == 1) ? g_hlo : g_h1lo;
    const __nv_bfloat16* __restrict__ whi = (MODE == 1) ? g_w1hi : g_w2hi;
    const __nv_bfloat16* __restrict__ wlo = (MODE == 1) ? g_w1lo : g_w2lo;
    const int* __restrict__ pin  = (MODE == 1) ? g_in1  : g_in2;
    const int* __restrict__ pout = (MODE == 1) ? g_out1 : g_out2;
    float* __restrict__ dstbase  = (MODE == 1) ? g_h1acc : ext_out;

    const int t = threadIdx.x;
    if (t < 128) {
        sIdx[t] = pin[base + t];
        sOut[t] = pout[base + t];
    }
    __syncthreads();

    const unsigned uAhi = smem_u32(Ahi), uAlo = smem_u32(Alo);
    const unsigned uBhi = smem_u32(Bhi), uBlo = smem_u32(Blo);

    const int warp = t >> 5, lane = t & 31;
    const int g = lane >> 2, tid = lane & 3;
    const int wm = (warp & 3) * 32;
    const int wn = (warp >> 2) * 64;

    const int a_row  = lane & 15;
    const int a_koff = (lane >> 4) * 16;
    const int b_row  = (lane & 7) + (lane >> 4) * 8;
    const int b_koff = ((lane >> 3) & 1) * 16;

    float acc[2][8][4];
    #pragma unroll
    for (int i = 0; i < 2; ++i)
        #pragma unroll
        for (int j = 0; j < 8; ++j)
            #pragma unroll
            for (int q = 0; q < 4; ++q) acc[i][j][q] = 0.f;

    const size_t wko = (size_t)k * 128 * CIN;

    const int r0 = t >> 2, j0 = t & 3;
    const int r1 = 64 + r0;
    const size_t a0b = (size_t)sIdx[r0] * CIN;
    const size_t a1b = (size_t)sIdx[r1] * CIN;
    const size_t b0b = wko + (size_t)r0 * CIN;
    const size_t b1b = wko + (size_t)r1 * CIN;
    const int to0 = r0 * LDB + j0 * 16;
    const int to1 = r1 * LDB + j0 * 16;

    uint4 P[2][8];
    #pragma unroll
    for (int sl = 0; sl < 2; ++sl) {
        const int c0 = sl * BK;
        P[sl][0] = *((const uint4*)(shi + a0b + c0) + j0);
        P[sl][1] = *((const uint4*)(slo + a0b + c0) + j0);
        P[sl][2] = *((const uint4*)(whi + b0b + c0) + j0);
        P[sl][3] = *((const uint4*)(wlo + b0b + c0) + j0);
        P[sl][4] = *((const uint4*)(shi + a1b + c0) + j0);
        P[sl][5] = *((const uint4*)(slo + a1b + c0) + j0);
        P[sl][6] = *((const uint4*)(whi + b1b + c0) + j0);
        P[sl][7] = *((const uint4*)(wlo + b1b + c0) + j0);
    }

    #pragma unroll
    for (int ch = 0; ch < NCH; ++ch) {
        const int sl = ch & 1;
        *(uint4*)((char*)Ahi + to0) = P[sl][0];
        *(uint4*)((char*)Alo + to0) = P[sl][1];
        *(uint4*)((char*)Bhi + to0) = P[sl][2];
        *(uint4*)((char*)Blo + to0) = P[sl][3];
        *(uint4*)((char*)Ahi + to1) = P[sl][4];
        *(uint4*)((char*)Alo + to1) = P[sl][5];
        *(uint4*)((char*)Bhi + to1) = P[sl][6];
        *(uint4*)((char*)Blo + to1) = P[sl][7];
        __syncthreads();

        if (ch + 2 < NCH) {
            const int c0 = (ch + 2) * BK;
            P[sl][0] = *((const uint4*)(shi + a0b + c0) + j0);
            P[sl][1] = *((const uint4*)(slo + a0b + c0) + j0);
            P[sl][2] = *((const uint4*)(whi + b0b + c0) + j0);
            P[sl][3] = *((const uint4*)(wlo + b0b + c0) + j0);
            P[sl][4] = *((const uint4*)(shi + a1b + c0) + j0);
            P[sl][5] = *((const uint4*)(slo + a1b + c0) + j0);
            P[sl][6] = *((const uint4*)(whi + b1b + c0) + j0);
            P[sl][7] = *((const uint4*)(wlo + b1b + c0) + j0);
        }

        #pragma unroll
        for (int ks = 0; ks < BK / 16; ++ks) {
            const int akb = ks * 32 + a_koff;
            const int bkb = ks * 32 + b_koff;
            unsigned ah[2][4], al[2][4];
            #pragma unroll
            for (int mt = 0; mt < 2; ++mt) {
                unsigned aoff = (unsigned)((wm + mt * 16 + a_row) * LDB + akb);
                ldsm4(ah[mt], uAhi + aoff);
                ldsm4(al[mt], uAlo + aoff);
            }
            #pragma unroll
            for (int n2 = 0; n2 < 4; ++n2) {
                unsigned boff = (unsigned)((wn + n2 * 16 + b_row) * LDB + bkb);
                unsigned bh[4], bl[4];
                ldsm4(bh, uBhi + boff);
                ldsm4(bl, uBlo + boff);
                #pragma unroll
                for (int mt = 0; mt < 2; ++mt) {
                    mma16816(acc[mt][n2 * 2],     ah[mt], bh);
                    mma16816(acc[mt][n2 * 2],     ah[mt], bl);
                    mma16816(acc[mt][n2 * 2],     al[mt], bh);
                    mma16816(acc[mt][n2 * 2 + 1], ah[mt], bh + 2);
                    mma16816(acc[mt][n2 * 2 + 1], ah[mt], bl + 2);
                    mma16816(acc[mt][n2 * 2 + 1], al[mt], bh + 2);
                }
            }
        }
        __syncthreads();
    }

    // ---- epilogue: smem transpose -> coalesced red.v4 scatter ----
    const int myp = (warp & 3) >> 1;
    const int cq = tid * 2;
    #pragma unroll
    for (int p = 0; p < 2; ++p) {
        if (myp == p) {
            #pragma unroll
            for (int mt = 0; mt < 2; ++mt)
                #pragma unroll
                for (int half = 0; half < 2; ++half) {
                    int lrow = (wm & 63) + mt * 16 + g + half * 8;
                    #pragma unroll
                    for (int na = 0; na < 8; ++na) {
                        int col = wn + na * 8 + cq;
                        *(float2*)&T[lrow * 132 + col] =
                            make_float2(acc[mt][na][half * 2],
                                        acc[mt][na][half * 2 + 1]);
                    }
                }
        }
        __syncthreads();
        #pragma unroll
        for (int i = 0; i < 8; ++i) {
            int lrow = i * 8 + warp;
            int cpos = lane * 4;
            int orow = sOut[p * 64 + lrow];
            if (orow >= 0) {
                float4 v = *(const float4*)&T[lrow * 132 + cpos];
                red_v4(dstbase + (size_t)orow * kCO + cpos, v);
            }
        }
        __syncthreads();
    }
}

// ---------------- h1 epilogue: +bias -> LN -> SiLU -> bf16 hi/lo -------------
__global__ void h1_ep_kernel(const float* __restrict__ c1b) {
    const int m = blockIdx.x, t = threadIdx.x;   // 128
    const int wid = t >> 5, lane = t & 31;
    __shared__ float red[4];
    float x = g_h1acc[m * kCO + t] + c1b[t];
    float s = x;
    #pragma unroll
    for (int o = 16; o; o >>= 1) s += __shfl_xor_sync(0xffffffffu, s, o);
    if (lane == 0) red[wid] = s;
    __syncthreads();
    const float mean = (red[0] + red[1] + red[2] + red[3]) * (1.f / kCO);
    const float d = x - mean;
    float s2 = d * d;
    #pragma unroll
    for (int o = 16; o; o >>= 1) s2 += __shfl_xor_sync(0xffffffffu, s2, o);
    __syncthreads();
    if (lane == 0) red[wid] = s2;
    __syncthreads();
    const float var = (red[0] + red[1] + red[2] + red[3]) * (1.f / kCO);
    const float y = d * rsqrtf(var + 1e-6f);
    const float h = y / (1.f + expf(-y));
    __nv_bfloat16 hh = __float2bfloat16(h);
    g_h1hi[m * kCO + t] = hh;
    g_h1lo[m * kCO + t] = __float2bfloat16(h - __bfloat162float(hh));
}

// ---------------- out epilogue: += c2 bias + skip acc + skip bias ------------
__global__ void out_ep_kernel(float* __restrict__ out,
                              const float* __restrict__ c2b,
                              const float* __restrict__ skb) {
    if ((int)blockIdx.x >= g_cnt) return;
    const int m = g_list[blockIdx.x], t = threadIdx.x;   // 128
    out[(size_t)m * kCO + t] +=
        c2b[t] + skb[t] + g_h1acc[(size_t)(kM + (m >> 3)) * kCO + t];
}

// ---------------- launch (ONLY harness pointers cross the boundary) ----------
extern "C" void kernel_launch(void* const* d_in, const int* in_sizes, int n_in,
                              void* d_out, int out_size)
{
    const float* feats = (const float*)d_in[0];
    const float* n1w   = (const float*)d_in[1];
    const float* n1b   = (const float*)d_in[2];
    const float* sdw   = (const float*)d_in[3];
    const float* sdb   = (const float*)d_in[4];
    const float* c1w   = (const float*)d_in[5];
    const float* c1b   = (const float*)d_in[6];
    const float* c2w   = (const float*)d_in[7];
    const float* c2b   = (const float*)d_in[8];
    const float* skw   = (const float*)d_in[9];
    const float* skb   = (const float*)d_in[10];
    const int*   coords= (const int*)d_in[11];

    float* out        = (float*)d_out;
    float* subdiv_out = out + (size_t)kM * kCO;

    prep_kernel<<<PREP_BLOCKS, 256>>>(out, c1w, c2w, skw);
    scatter_kernel<<<kM / 256, 256>>>(coords);        // MUST follow sentinel fill
    row_kernel<<<kN, 256>>>(feats, n1w, n1b, sdw, sdb, subdiv_out);
    nidx_kernel<<<dim3(kM / 256, 9), 256>>>(coords);
    tap_scan_kernel<<<1, 32>>>();
    tap_fill_kernel<<<55, 256>>>();
    tapgemm_mma<1><<<28 * 128, 256>>>(nullptr);       // conv1 taps + skip GEMM
    h1_ep_kernel<<<kM, 128>>>(c1b);
    tapgemm_mma<2><<<27 * 128, 256>>>(out);
    out_ep_kernel<<<kM, 128>>>(out, c2b, skb);
}